// round 16
// baseline (speedup 1.0000x reference)
#include <cuda_runtime.h>
#include <math.h>
#include <stdint.h>

// Problem constants
#define Bn 32
#define Cn 8
#define HWn 65536     // 256*256

#define BLOCKS_PER_BG 8
#define NBG 64                           // Bn * Gn
#define NBLK 512                         // NBG * BLOCKS_PER_BG, single wave
#define THREADS 128
#define ITERS 16
// pixels per block = HWn / BLOCKS_PER_BG = 8192 = 2048 float4/plane = 16 x 128

// sigmoid(x) > 0.7  <=>  x > ln(0.7/0.3)
#define LOGIT_THRESH 0.8472978603872037f

// Deterministic scratch: one float4 per block: {bce, msum, cnt, dsum}
__device__ float4 g_partial[NBLK];
__device__ unsigned int g_done;   // zero-init; reset by finalizer each run

__device__ __forceinline__ void cp_async16(uint32_t smem_dst, const void* gmem_src)
{
    asm volatile("cp.async.cg.shared.global [%0], [%1], 16;\n"
                 :: "r"(smem_dst), "l"(gmem_src));
}
__device__ __forceinline__ void cp_commit()
{
    asm volatile("cp.async.commit_group;\n");
}

__device__ __forceinline__ void compute8(const float4* v,
    float& bce, float& msum, float& cnt, float& dsum)
{
    float oc[4][4], tc[4][4];
    #pragma unroll
    for (int k = 0; k < 4; k++) {
        oc[k][0] = v[k].x;     oc[k][1] = v[k].y;
        oc[k][2] = v[k].z;     oc[k][3] = v[k].w;
        tc[k][0] = v[k + 4].x; tc[k][1] = v[k + 4].y;
        tc[k][2] = v[k + 4].z; tc[k][3] = v[k + 4].w;
    }
    #pragma unroll
    for (int j = 0; j < 4; j++) {
        const float x  = oc[3][j];
        const float tm = tc[3][j];
        // t*log(p) + (1-t)*log1p(-p) == t*x - softplus(x) exactly.
        // softplus(x) = max(x,0) + log(1 + exp(-|x|)), MUFU-only.
        const float sp = fmaxf(x, 0.f) + __logf(1.f + __expf(-fabsf(x)));
        bce += tm * x - sp;

        const float d0 = oc[0][j] - tc[0][j];
        const float d1 = oc[1][j] - tc[1][j];
        const float d2 = oc[2][j] - tc[2][j];
        const float dn = sqrtf(d0 * d0 + d1 * d1 + d2 * d2);
        dsum += dn;
        if (x > LOGIT_THRESH) {
            msum += dn;
            cnt  += (dn != 0.f) ? 1.f : 0.f;
        }
    }
}

__global__ void __launch_bounds__(THREADS, 6) lpmask_fused(
    const float* __restrict__ out, const float* __restrict__ tar,
    float* __restrict__ result)
{
    // Depth-2 ping-pong staging buffer: [stage][plane][thread] float4.
    // Each thread prefetches AND consumes only its own slots -> no barriers.
    __shared__ float4 buf[2][8][THREADS];   // 32 KB
    __shared__ float s[4][4];

    const int bgid = blockIdx.x >> 3;              // 0..63  (b*2+g)
    const int blk  = blockIdx.x & 7;               // 0..7
    const int b = bgid >> 1;
    const int g = bgid & 1;

    const size_t base = (size_t)b * Cn * HWn + (size_t)g * 4 * HWn;
    const int plane4 = HWn / 4;                    // 16384 float4 per plane
    const int start  = blk * (ITERS * THREADS) + threadIdx.x;

    const float4* pl[8];
    pl[0] = (const float4*)(out + base) + start;
    pl[1] = pl[0] + plane4;
    pl[2] = pl[0] + 2 * plane4;
    pl[3] = pl[0] + 3 * plane4;
    pl[4] = (const float4*)(tar + base) + start;
    pl[5] = pl[4] + plane4;
    pl[6] = pl[4] + 2 * plane4;
    pl[7] = pl[4] + 3 * plane4;

    const uint32_t sbase =
        (uint32_t)__cvta_generic_to_shared(&buf[0][0][threadIdx.x]);
    const uint32_t stage_stride = 8u * THREADS * 16u;   // bytes per stage
    const uint32_t plane_stride = (uint32_t)THREADS * 16u;

    float bce  = 0.f;
    float msum = 0.f;
    float cnt  = 0.f;
    float dsum = 0.f;

    // Prefetch iteration 0 into stage 0
    {
        const uint32_t dst = sbase;
        #pragma unroll
        for (int p = 0; p < 8; p++)
            cp_async16(dst + p * plane_stride, pl[p]);
        cp_commit();
    }

    #pragma unroll
    for (int it = 0; it < ITERS; it++) {
        const int cur = it & 1;
        if (it + 1 < ITERS) {
            // Prefetch next iteration into the other stage
            const uint32_t dst = sbase + (cur ^ 1) * stage_stride;
            const int nidx = (it + 1) * THREADS;
            #pragma unroll
            for (int p = 0; p < 8; p++)
                cp_async16(dst + p * plane_stride, pl[p] + nidx);
            cp_commit();
            asm volatile("cp.async.wait_group 1;\n");   // stage 'cur' ready
        } else {
            asm volatile("cp.async.wait_group 0;\n");
        }

        float4 v[8];
        #pragma unroll
        for (int p = 0; p < 8; p++)
            v[p] = buf[cur][p][threadIdx.x];
        compute8(v, bce, msum, cnt, dsum);
    }

    // ---- Block reduction (4 warps) ----
    #pragma unroll
    for (int off = 16; off > 0; off >>= 1) {
        bce  += __shfl_down_sync(0xffffffffu, bce,  off);
        msum += __shfl_down_sync(0xffffffffu, msum, off);
        cnt  += __shfl_down_sync(0xffffffffu, cnt,  off);
        dsum += __shfl_down_sync(0xffffffffu, dsum, off);
    }

    const int lane = threadIdx.x & 31;
    const int warp = threadIdx.x >> 5;
    if (lane == 0) {
        s[warp][0] = bce; s[warp][1] = msum; s[warp][2] = cnt; s[warp][3] = dsum;
    }
    __syncthreads();

    if (warp != 0) return;

    int is_last = 0;
    if (lane == 0) {
        float v0 = 0.f, v1 = 0.f, v2 = 0.f, v3 = 0.f;
        #pragma unroll
        for (int w = 0; w < 4; w++) {
            v0 += s[w][0]; v1 += s[w][1]; v2 += s[w][2]; v3 += s[w][3];
        }
        g_partial[blockIdx.x] = make_float4(v0, v1, v2, v3);
        __threadfence();
        const unsigned int prev = atomicAdd(&g_done, 1u);
        is_last = (prev == NBLK - 1) ? 1 : 0;
    }
    is_last = __shfl_sync(0xffffffffu, is_last, 0);
    if (!is_last) return;

    // ---- Very last warp on the GPU: finalize from L2-resident partials ----
    // loss = 0.7*(-sum_bce)/(NBG*HW) + 0.3*(sum_per_sample)/NBG
    // Lane l owns bg = l and bg = l + 32 (8 partial rows each).
    float ps_tot  = 0.f;
    float bce_tot = 0.f;
    #pragma unroll
    for (int half = 0; half < 2; half++) {
        const int my_bg = lane + half * 32;
        float b2 = 0.f, m2 = 0.f, c2 = 0.f, d2 = 0.f;
        #pragma unroll
        for (int i = 0; i < BLOCKS_PER_BG; i++) {
            const float4 q = g_partial[my_bg * BLOCKS_PER_BG + i];
            b2 += q.x; m2 += q.y; c2 += q.z; d2 += q.w;
        }
        const float fallback   = d2 * (1.f / (float)HWn);
        const float per_sample = (c2 > 0.f) ? (m2 / fmaxf(c2, 1.f)) : fallback;
        ps_tot  += per_sample;
        bce_tot += b2;
    }
    #pragma unroll
    for (int off = 16; off > 0; off >>= 1) {
        ps_tot  += __shfl_down_sync(0xffffffffu, ps_tot,  off);
        bce_tot += __shfl_down_sync(0xffffffffu, bce_tot, off);
    }
    if (lane == 0) {
        const float mask_loss = -bce_tot / ((float)NBG * (float)HWn);
        const float nocs_loss = ps_tot * (1.f / (float)NBG);
        result[0] = 0.7f * mask_loss + 0.3f * nocs_loss;
        g_done = 0u;   // reset for next graph replay
    }
}

extern "C" void kernel_launch(void* const* d_in, const int* in_sizes, int n_in,
                              void* d_out, int out_size)
{
    const float* output = (const float*)d_in[0];
    const float* target = (const float*)d_in[1];
    float* out = (float*)d_out;

    lpmask_fused<<<NBLK, THREADS>>>(output, target, out);
}

// round 17
// speedup vs baseline: 1.2106x; 1.2106x over previous
#include <cuda_runtime.h>
#include <math.h>

// Problem constants
#define Bn 32
#define Cn 8
#define HWn 65536     // 256*256

#define BLOCKS_PER_BG 16
#define NBG 64                           // Bn * Gn
#define NBLK 1024                        // NBG * BLOCKS_PER_BG, single wave
#define THREADS 128
#define ITERS 8
// pixels per block = HWn / BLOCKS_PER_BG = 4096 = 1024 float4 = 8 x 128 threads

// sigmoid(x) > 0.7  <=>  x > ln(0.7/0.3)
#define LOGIT_THRESH 0.8472978603872037f

// Level-1 scratch: one float4 per block: {bce, msum, cnt, dsum}
__device__ float4 g_partial[NBLK];
// Level-2 scratch: one float2 per bg: {bce_sum, per_sample}
__device__ float2 g_bg[NBG];
__device__ unsigned int g_done_bg[NBG];  // zero-init; reset by bg finalizers
__device__ unsigned int g_done;          // zero-init; reset by global finalizer

__global__ void __launch_bounds__(THREADS) lpmask_fused(
    const float* __restrict__ out, const float* __restrict__ tar,
    float* __restrict__ result)
{
    const int bgid = blockIdx.x >> 4;              // 0..63  (b*2+g)
    const int blk  = blockIdx.x & 15;              // 0..15
    const int b = bgid >> 1;
    const int g = bgid & 1;

    const size_t base = (size_t)b * Cn * HWn + (size_t)g * 4 * HWn;
    const int plane4 = HWn / 4;                    // 16384 float4 per plane
    const int start  = blk * (ITERS * THREADS) + threadIdx.x;

    // Per-plane base pointers (no per-load IMAD chains)
    const float4* __restrict__ po0 = (const float4*)(out + base) + start;
    const float4* __restrict__ po1 = po0 + plane4;
    const float4* __restrict__ po2 = po0 + 2 * plane4;
    const float4* __restrict__ po3 = po0 + 3 * plane4;
    const float4* __restrict__ pt0 = (const float4*)(tar + base) + start;
    const float4* __restrict__ pt1 = pt0 + plane4;
    const float4* __restrict__ pt2 = pt0 + 2 * plane4;
    const float4* __restrict__ pt3 = pt0 + 3 * plane4;

    float bce  = 0.f;
    float msum = 0.f;
    float cnt  = 0.f;
    float dsum = 0.f;

    #pragma unroll
    for (int it = 0; it < ITERS; it++) {
        const int idx = it * THREADS;

        // 8 batched streaming float4 loads (no reuse -> evict-first)
        float4 ov0 = __ldcs(po0 + idx), ov1 = __ldcs(po1 + idx);
        float4 ov2 = __ldcs(po2 + idx), ov3 = __ldcs(po3 + idx);
        float4 tv0 = __ldcs(pt0 + idx), tv1 = __ldcs(pt1 + idx);
        float4 tv2 = __ldcs(pt2 + idx), tv3 = __ldcs(pt3 + idx);

        float oc[4][4], tc[4][4];
        oc[0][0]=ov0.x; oc[0][1]=ov0.y; oc[0][2]=ov0.z; oc[0][3]=ov0.w;
        oc[1][0]=ov1.x; oc[1][1]=ov1.y; oc[1][2]=ov1.z; oc[1][3]=ov1.w;
        oc[2][0]=ov2.x; oc[2][1]=ov2.y; oc[2][2]=ov2.z; oc[2][3]=ov2.w;
        oc[3][0]=ov3.x; oc[3][1]=ov3.y; oc[3][2]=ov3.z; oc[3][3]=ov3.w;
        tc[0][0]=tv0.x; tc[0][1]=tv0.y; tc[0][2]=tv0.z; tc[0][3]=tv0.w;
        tc[1][0]=tv1.x; tc[1][1]=tv1.y; tc[1][2]=tv1.z; tc[1][3]=tv1.w;
        tc[2][0]=tv2.x; tc[2][1]=tv2.y; tc[2][2]=tv2.z; tc[2][3]=tv2.w;
        tc[3][0]=tv3.x; tc[3][1]=tv3.y; tc[3][2]=tv3.z; tc[3][3]=tv3.w;

        #pragma unroll
        for (int j = 0; j < 4; j++) {
            const float x  = oc[3][j];
            const float tm = tc[3][j];
            // t*log(p) + (1-t)*log1p(-p) == t*x - softplus(x) exactly.
            // softplus(x) = max(x,0) + log(1 + exp(-|x|)), MUFU-only.
            const float sp = fmaxf(x, 0.f) + __logf(1.f + __expf(-fabsf(x)));
            bce += tm * x - sp;

            const float d0 = oc[0][j] - tc[0][j];
            const float d1 = oc[1][j] - tc[1][j];
            const float d2 = oc[2][j] - tc[2][j];
            const float dn = sqrtf(d0 * d0 + d1 * d1 + d2 * d2);
            dsum += dn;
            if (x > LOGIT_THRESH) {
                msum += dn;
                cnt  += (dn != 0.f) ? 1.f : 0.f;
            }
        }
    }

    // ---- Block reduction (4 warps) ----
    #pragma unroll
    for (int off = 16; off > 0; off >>= 1) {
        bce  += __shfl_down_sync(0xffffffffu, bce,  off);
        msum += __shfl_down_sync(0xffffffffu, msum, off);
        cnt  += __shfl_down_sync(0xffffffffu, cnt,  off);
        dsum += __shfl_down_sync(0xffffffffu, dsum, off);
    }

    __shared__ float s[4][4];
    const int lane = threadIdx.x & 31;
    const int warp = threadIdx.x >> 5;
    if (lane == 0) {
        s[warp][0] = bce; s[warp][1] = msum; s[warp][2] = cnt; s[warp][3] = dsum;
    }
    __syncthreads();

    // Warps 1..3 retire; warp 0 owns the whole tail.
    if (warp != 0) return;

    // --- Level 1: publish block partial, count within bg ---
    int is_bg_last = 0;
    if (lane == 0) {
        float v0 = 0.f, v1 = 0.f, v2 = 0.f, v3 = 0.f;
        #pragma unroll
        for (int w = 0; w < 4; w++) {
            v0 += s[w][0]; v1 += s[w][1]; v2 += s[w][2]; v3 += s[w][3];
        }
        g_partial[blockIdx.x] = make_float4(v0, v1, v2, v3);
        __threadfence();
        const unsigned int prev = atomicAdd(&g_done_bg[bgid], 1u);
        is_bg_last = (prev == BLOCKS_PER_BG - 1) ? 1 : 0;
    }
    is_bg_last = __shfl_sync(0xffffffffu, is_bg_last, 0);
    if (!is_bg_last) return;

    // --- Level 2: last block of this bg reduces its 16 rows (overlapped
    //     with other bgs still streaming) ---
    __threadfence();   // acquire: order partial reads after counter observation
    float b2 = 0.f, m2 = 0.f, c2 = 0.f, d2 = 0.f;
    if (lane < BLOCKS_PER_BG) {
        const float4 q = g_partial[bgid * BLOCKS_PER_BG + lane];
        b2 = q.x; m2 = q.y; c2 = q.z; d2 = q.w;
    }
    #pragma unroll
    for (int off = 8; off > 0; off >>= 1) {
        b2 += __shfl_down_sync(0xffffffffu, b2, off);
        m2 += __shfl_down_sync(0xffffffffu, m2, off);
        c2 += __shfl_down_sync(0xffffffffu, c2, off);
        d2 += __shfl_down_sync(0xffffffffu, d2, off);
    }

    int is_last = 0;
    if (lane == 0) {
        const float fallback   = d2 * (1.f / (float)HWn);
        const float per_sample = (c2 > 0.f) ? (m2 / fmaxf(c2, 1.f)) : fallback;
        g_bg[bgid] = make_float2(b2, per_sample);
        g_done_bg[bgid] = 0u;   // reset for next graph replay
        __threadfence();
        const unsigned int prev = atomicAdd(&g_done, 1u);
        is_last = (prev == NBG - 1) ? 1 : 0;
    }
    is_last = __shfl_sync(0xffffffffu, is_last, 0);
    if (!is_last) return;

    // --- Level 3: global finalize — only 64 float2 left ---
    __threadfence();
    float bce_tot = 0.f, ps_tot = 0.f;
    {
        const float2 qa = g_bg[lane];
        const float2 qb = g_bg[lane + 32];
        bce_tot = qa.x + qb.x;
        ps_tot  = qa.y + qb.y;
    }
    #pragma unroll
    for (int off = 16; off > 0; off >>= 1) {
        bce_tot += __shfl_down_sync(0xffffffffu, bce_tot, off);
        ps_tot  += __shfl_down_sync(0xffffffffu, ps_tot,  off);
    }
    if (lane == 0) {
        const float mask_loss = -bce_tot / ((float)NBG * (float)HWn);
        const float nocs_loss = ps_tot * (1.f / (float)NBG);
        result[0] = 0.7f * mask_loss + 0.3f * nocs_loss;
        g_done = 0u;   // reset for next graph replay
    }
}

extern "C" void kernel_launch(void* const* d_in, const int* in_sizes, int n_in,
                              void* d_out, int out_size)
{
    const float* output = (const float*)d_in[0];
    const float* target = (const float*)d_in[1];
    float* out = (float*)d_out;

    lpmask_fused<<<NBLK, THREADS>>>(output, target, out);
}